// round 3
// baseline (speedup 1.0000x reference)
#include <cuda_runtime.h>
#include <math.h>

#define HIDN 128
#define LATN 64
#define AFN 10
#define NBATCH 512
#define NATOMS 58
#define NNODE (NBATCH*NATOMS)     // 29696
#define EDGES (NNODE*16)          // 475136
#define AST 132                   // padded smem stride for transposed A tiles

// ---------------- scratch (device globals; no runtime allocation) ----------------
__device__ float g_h  [NNODE*HIDN];
__device__ float g_pa [NNODE*HIDN];
__device__ float g_pb [NNODE*HIDN];
__device__ float g_agg[NNODE*HIDN];
__device__ float g_zh [NBATCH*HIDN];
__device__ float g_h1 [(size_t)EDGES*HIDN];   // 243 MB
__device__ float g_rel[EDGES*3];
__device__ float g_d2 [EDGES];
__device__ float g_pos[NNODE*3];
__device__ float g_upd[NNODE*3];
__device__ float g_deg[NNODE];

__device__ __forceinline__ float siluf(float x){ return x / (1.0f + expf(-x)); }

// ---------------- tile helpers: 256 threads, block tile 128x128, thread tile 8x8 ----
// As is stored transposed: As[k*AST + r]  (k = reduction idx, r = row in tile)
__device__ __forceinline__ void stageA(const float* __restrict__ g, float* As, int tid){
    // g: row-major [128][128] tile start
#pragma unroll
    for (int i = 0; i < 16; i++){
        int idx4 = tid + i*256;          // 0..4095 float4s
        int r  = idx4 >> 5;              // row
        int kq = idx4 & 31;              // float4 index along K
        float4 v = ((const float4*)g)[r*32 + kq];
        int k0 = kq*4;
        As[(k0+0)*AST + r] = v.x;
        As[(k0+1)*AST + r] = v.y;
        As[(k0+2)*AST + r] = v.z;
        As[(k0+3)*AST + r] = v.w;
    }
}

__device__ __forceinline__ void stageB(const float* __restrict__ g, float* Bs, int tid){
    // plain copy of [128][128] row-major weights
#pragma unroll
    for (int i = 0; i < 16; i++){
        int f4 = tid + i*256;
        ((float4*)Bs)[f4] = ((const float4*)g)[f4];
    }
}

__device__ __forceinline__ void gemm128(const float* As, const float* Bs,
                                        int r0, int c0, float acc[8][8]){
#pragma unroll 8
    for (int k = 0; k < 128; k++){
        float4 a0 = *(const float4*)(As + k*AST + r0);
        float4 a1 = *(const float4*)(As + k*AST + r0 + 4);
        float4 b0 = *(const float4*)(Bs + k*HIDN + c0);
        float4 b1 = *(const float4*)(Bs + k*HIDN + c0 + 4);
        float a[8] = {a0.x,a0.y,a0.z,a0.w,a1.x,a1.y,a1.z,a1.w};
        float b[8] = {b0.x,b0.y,b0.z,b0.w,b1.x,b1.y,b1.z,b1.w};
#pragma unroll
        for (int i = 0; i < 8; i++)
#pragma unroll
            for (int j = 0; j < 8; j++)
                acc[i][j] += a[i]*b[j];
    }
}

__device__ __forceinline__ void writeTile(float* __restrict__ g, int r0, int c0, float acc[8][8]){
#pragma unroll
    for (int i = 0; i < 8; i++){
        float4 v0 = make_float4(acc[i][0],acc[i][1],acc[i][2],acc[i][3]);
        float4 v1 = make_float4(acc[i][4],acc[i][5],acc[i][6],acc[i][7]);
        *(float4*)(g + (size_t)(r0+i)*HIDN + c0)     = v0;
        *(float4*)(g + (size_t)(r0+i)*HIDN + c0 + 4) = v1;
    }
}

// ---------------- init kernels ----------------
__global__ void k_zero_deg(){
    int i = blockIdx.x*blockDim.x + threadIdx.x;
    if (i < NNODE) g_deg[i] = 0.0f;
}
__global__ void k_deg(const int* __restrict__ eidx){
    int e = blockIdx.x*blockDim.x + threadIdx.x;
    if (e < EDGES) atomicAdd(&g_deg[eidx[e]], 1.0f);
}
__global__ void k_zh(const float* __restrict__ z, const float* __restrict__ lw,
                     const float* __restrict__ lb){
    int b = blockIdx.x, c = threadIdx.x;
    float acc = lb[c];
#pragma unroll 8
    for (int k = 0; k < LATN; k++) acc += z[b*LATN + k] * lw[k*HIDN + c];
    g_zh[b*HIDN + c] = acc;
}
__global__ void k_hinit(const float* __restrict__ at, const float* __restrict__ aw,
                        const float* __restrict__ ab){
    int n = blockIdx.x, c = threadIdx.x;
    float acc = g_zh[(n / NATOMS)*HIDN + c] + ab[c];
#pragma unroll
    for (int j = 0; j < AFN; j++) acc += at[n*AFN + j] * aw[j*HIDN + c];
    g_h[(size_t)n*HIDN + c] = acc;
}
__global__ void k_posinit(const float* __restrict__ ic){
    int i = blockIdx.x*blockDim.x + threadIdx.x;
    if (i < NNODE*3){
        int n = i / 3, j = i - n*3;
        g_pos[i] = ic[(n % NATOMS)*3 + j];
    }
}
__global__ void k_zero_layer(){
    int i = blockIdx.x*blockDim.x + threadIdx.x;
    if (i < NNODE*HIDN) g_agg[i] = 0.0f;
    if (i < NNODE*3)    g_upd[i] = 0.0f;
}

// ---------------- per-layer kernels ----------------
// pa = h @ W1a, pb = h @ W1b   (W1a = ew1 rows 0..127, W1b = rows 128..255)
__global__ void __launch_bounds__(256) k_papb(const float* __restrict__ ew1, int layer){
    extern __shared__ float sm[];
    float* As = sm;
    float* Bs = sm + 128*AST;
    int tid = threadIdx.x;
    int n0 = blockIdx.x*128;
    int r0 = (tid >> 4)*8, c0 = (tid & 15)*8;
    const float* W = ew1 + (size_t)layer*257*HIDN;

    stageA(g_h + (size_t)n0*HIDN, As, tid);
    stageB(W, Bs, tid);
    __syncthreads();
    float acc[8][8] = {};
    gemm128(As, Bs, r0, c0, acc);
    writeTile(g_pa + (size_t)n0*HIDN, r0, c0, acc);
    __syncthreads();
    stageB(W + 128*HIDN, Bs, tid);
    __syncthreads();
    float acc2[8][8] = {};
    gemm128(As, Bs, r0, c0, acc2);
    writeTile(g_pb + (size_t)n0*HIDN, r0, c0, acc2);
}

__global__ void k_reld2(const int* __restrict__ eidx){
    int e = blockIdx.x*blockDim.x + threadIdx.x;
    if (e >= EDGES) return;
    int r = eidx[e], c = eidx[EDGES + e];
    float rx = g_pos[r*3+0] - g_pos[c*3+0];
    float ry = g_pos[r*3+1] - g_pos[c*3+1];
    float rz = g_pos[r*3+2] - g_pos[c*3+2];
    float d2 = rx*rx + ry*ry + rz*rz;
    d2 = fminf(fmaxf(d2, 1e-6f), 1e6f);
    g_rel[e*3+0] = rx; g_rel[e*3+1] = ry; g_rel[e*3+2] = rz;
    g_d2[e] = d2;
}

// h1 = silu(pa[row] + pb[col] + d2*w1c + eb1)
__global__ void k_edge1(const float* __restrict__ ew1, const float* __restrict__ eb1,
                        const int* __restrict__ eidx, int layer){
    int idx = blockIdx.x*blockDim.x + threadIdx.x;   // covers EDGES*HIDN exactly
    int e = idx >> 7, c = idx & 127;
    int r  = eidx[e];
    int cl = eidx[EDGES + e];
    const float* base = ew1 + (size_t)layer*257*HIDN;
    float pre = g_pa[(size_t)r*HIDN + c] + g_pb[(size_t)cl*HIDN + c]
              + g_d2[e]*base[256*HIDN + c] + eb1[layer*HIDN + c];
    g_h1[(size_t)idx] = siluf(pre);
}

// m = silu(h1@ew2 + eb2); cw = clip(silu(m@cw1+cb1)@cw2); agg[row]+=m; upd[row]+=cw*rel
__global__ void __launch_bounds__(256) k_edge2(const float* __restrict__ ew2,
        const float* __restrict__ eb2,  const float* __restrict__ cw1,
        const float* __restrict__ cb1,  const float* __restrict__ cw2,
        const int* __restrict__ eidx, int layer){
    extern __shared__ float sm[];
    float* As   = sm;                    // 128*132
    float* Bs   = As + 128*AST;          // ew2
    float* Bs2  = Bs + 128*128;          // cw1
    float* red2 = Bs2 + 128*128;         // 128*17
    int*  rows_s = (int*)(red2 + 128*17);// 128 ints
    int tid = threadIdx.x;
    int e0 = blockIdx.x*128;
    int r0 = (tid >> 4)*8, c0 = (tid & 15)*8;

    stageA(g_h1 + (size_t)e0*HIDN, As, tid);
    stageB(ew2 + (size_t)layer*HIDN*HIDN, Bs, tid);
    stageB(cw1 + (size_t)layer*HIDN*HIDN, Bs2, tid);
    if (tid < 128) rows_s[tid] = eidx[e0 + tid];
    __syncthreads();

    float acc[8][8] = {};
    gemm128(As, Bs, r0, c0, acc);
    float bb[8];
#pragma unroll
    for (int j = 0; j < 8; j++) bb[j] = eb2[layer*HIDN + c0 + j];
    float m[8][8];
#pragma unroll
    for (int i = 0; i < 8; i++)
#pragma unroll
        for (int j = 0; j < 8; j++) m[i][j] = siluf(acc[i][j] + bb[j]);
    __syncthreads();                    // all reads of As done

    // stage m transposed back into As for GEMM2
#pragma unroll
    for (int j = 0; j < 8; j++)
#pragma unroll
        for (int i = 0; i < 8; i++)
            As[(c0+j)*AST + r0 + i] = m[i][j];
    __syncthreads();

    float acc2[8][8] = {};
    gemm128(As, Bs2, r0, c0, acc2);
    float cb[8], c2v[8];
#pragma unroll
    for (int j = 0; j < 8; j++){
        cb[j]  = cb1[layer*HIDN + c0 + j];
        c2v[j] = cw2[layer*HIDN + c0 + j];
    }
#pragma unroll
    for (int i = 0; i < 8; i++){
        float p = 0.0f;
#pragma unroll
        for (int j = 0; j < 8; j++){
            float c1 = siluf(acc2[i][j] + cb[j]);
            p += c1 * c2v[j];
        }
        red2[(r0+i)*17 + (tid & 15)] = p;
    }
    __syncthreads();

    if (tid < 128){
        float s = 0.0f;
#pragma unroll
        for (int t = 0; t < 16; t++) s += red2[tid*17 + t];
        float cwv = fminf(fmaxf(s, -1.0f), 1.0f);
        int e = e0 + tid;
        int rw = rows_s[tid];
        atomicAdd(&g_upd[rw*3+0], cwv * g_rel[e*3+0]);
        atomicAdd(&g_upd[rw*3+1], cwv * g_rel[e*3+1]);
        atomicAdd(&g_upd[rw*3+2], cwv * g_rel[e*3+2]);
    }

    // agg[row] += m : coalesced (warp = one edge row, consecutive columns)
#pragma unroll 4
    for (int i = 0; i < 64; i++){
        int flat = tid + i*256;
        int e = flat >> 7, c = flat & 127;
        atomicAdd(&g_agg[(size_t)rows_s[e]*HIDN + c], As[c*AST + e]);
    }
}

// hn = LN( silu([h,agg]@nw1 + nb1) @ nw2 + nb2 )  -> written back into g_h
__global__ void __launch_bounds__(256) k_node(const float* __restrict__ nw1,
        const float* __restrict__ nb1, const float* __restrict__ nw2,
        const float* __restrict__ nb2, const float* __restrict__ lg,
        const float* __restrict__ lb, int layer){
    extern __shared__ float sm[];
    float* As   = sm;             // 128*132 (also reused as Hs)
    float* Bs   = As + 128*AST;   // 128*128
    float* mu_s = Bs + 128*128;   // 128
    float* rs_s = mu_s + 128;     // 128
    int tid = threadIdx.x;
    int n0 = blockIdx.x*128;
    int r0 = (tid >> 4)*8, c0 = (tid & 15)*8;
    const float* W1 = nw1 + (size_t)layer*256*HIDN;

    float acc[8][8] = {};
    stageA(g_h + (size_t)n0*HIDN, As, tid);
    stageB(W1, Bs, tid);
    __syncthreads();
    gemm128(As, Bs, r0, c0, acc);
    __syncthreads();
    stageA(g_agg + (size_t)n0*HIDN, As, tid);
    stageB(W1 + 128*HIDN, Bs, tid);
    __syncthreads();
    gemm128(As, Bs, r0, c0, acc);
    __syncthreads();

    // t = silu(acc + nb1), staged transposed into As; Bs <- nw2
#pragma unroll
    for (int j = 0; j < 8; j++){
        float b = nb1[layer*HIDN + c0 + j];
#pragma unroll
        for (int i = 0; i < 8; i++)
            As[(c0+j)*AST + r0 + i] = siluf(acc[i][j] + b);
    }
    stageB(nw2 + (size_t)layer*HIDN*HIDN, Bs, tid);
    __syncthreads();

    float acc2[8][8] = {};
    gemm128(As, Bs, r0, c0, acc2);
    __syncthreads();                 // As reads done; reuse as Hs (row-major, stride AST)
#pragma unroll
    for (int i = 0; i < 8; i++){
#pragma unroll
        for (int j = 0; j < 8; j++)
            As[(r0+i)*AST + c0 + j] = acc2[i][j] + nb2[layer*HIDN + c0 + j];
    }
    __syncthreads();

    if (tid < 128){
        float s = 0.0f, s2 = 0.0f;
        const float* row = As + tid*AST;
#pragma unroll 8
        for (int k = 0; k < 128; k++){ float v = row[k]; s += v; s2 += v*v; }
        float mu = s * (1.0f/128.0f);
        float var = s2 * (1.0f/128.0f) - mu*mu;
        mu_s[tid] = mu;
        rs_s[tid] = rsqrtf(var + 1e-5f);
    }
    __syncthreads();

#pragma unroll
    for (int i = 0; i < 16; i++){
        int f4 = tid + i*256;
        int r = f4 >> 5, cq = f4 & 31, c = cq*4;
        float4 v = *(float4*)(As + r*AST + c);
        float mu = mu_s[r], rs = rs_s[r];
        v.x = (v.x - mu)*rs*lg[layer*HIDN + c+0] + lb[layer*HIDN + c+0];
        v.y = (v.y - mu)*rs*lg[layer*HIDN + c+1] + lb[layer*HIDN + c+1];
        v.z = (v.z - mu)*rs*lg[layer*HIDN + c+2] + lb[layer*HIDN + c+2];
        v.w = (v.w - mu)*rs*lg[layer*HIDN + c+3] + lb[layer*HIDN + c+3];
        *(float4*)(g_h + (size_t)(n0+r)*HIDN + c) = v;
    }
}

__global__ void k_posupd(){
    int i = blockIdx.x*blockDim.x + threadIdx.x;
    if (i < NNODE*3){
        int n = i / 3;
        g_pos[i] += g_upd[i] / (g_deg[n] + 1e-6f);
    }
}

// out = pos + silu(h@hw1+hb1)@hw2 + hb2
__global__ void __launch_bounds__(64) k_head(const float* __restrict__ hw1,
        const float* __restrict__ hb1, const float* __restrict__ hw2,
        const float* __restrict__ hb2, float* __restrict__ out){
    __shared__ float t[64];
    int tid = threadIdx.x;
    for (int u = 0; u < 8; u++){
        int n = blockIdx.x*8 + u;
        float acc = hb1[tid];
        const float* hr = g_h + (size_t)n*HIDN;
#pragma unroll 8
        for (int k = 0; k < 128; k++) acc += hr[k] * hw1[k*64 + tid];
        t[tid] = siluf(acc);
        __syncthreads();
        if (tid < 3){
            float d = hb2[tid];
#pragma unroll 8
            for (int k = 0; k < 64; k++) d += t[k] * hw2[k*3 + tid];
            out[n*3 + tid] = g_pos[n*3 + tid] + d;
        }
        __syncthreads();
    }
}

// ---------------- host ----------------
extern "C" void kernel_launch(void* const* d_in, const int* in_sizes, int n_in,
                              void* d_out, int out_size){
    const float* z   = (const float*)d_in[0];
    const float* at  = (const float*)d_in[1];
    const int*   eidx = (const int*)d_in[2];
    const float* ic  = (const float*)d_in[3];
    const float* lw  = (const float*)d_in[4];
    const float* lb  = (const float*)d_in[5];
    const float* aw  = (const float*)d_in[6];
    const float* ab  = (const float*)d_in[7];
    const float* ew1 = (const float*)d_in[8];
    const float* eb1 = (const float*)d_in[9];
    const float* ew2 = (const float*)d_in[10];
    const float* eb2 = (const float*)d_in[11];
    const float* nw1 = (const float*)d_in[12];
    const float* nb1 = (const float*)d_in[13];
    const float* nw2 = (const float*)d_in[14];
    const float* nb2 = (const float*)d_in[15];
    const float* cw1 = (const float*)d_in[16];
    const float* cb1 = (const float*)d_in[17];
    const float* cw2 = (const float*)d_in[18];
    const float* lg  = (const float*)d_in[19];
    const float* lbn = (const float*)d_in[20];
    const float* hw1 = (const float*)d_in[21];
    const float* hb1 = (const float*)d_in[22];
    const float* hw2 = (const float*)d_in[23];
    const float* hb2 = (const float*)d_in[24];

    const int SM_PAPB = (128*AST + 128*128) * 4;                       // 133,120 B
    const int SM_NODE = (128*AST + 128*128 + 256) * 4;                 // 134,144 B
    const int SM_E2   = (128*AST + 2*128*128 + 128*17) * 4 + 128*4;    // 207,872 B
    cudaFuncSetAttribute(k_papb,  cudaFuncAttributeMaxDynamicSharedMemorySize, SM_PAPB);
    cudaFuncSetAttribute(k_node,  cudaFuncAttributeMaxDynamicSharedMemorySize, SM_NODE);
    cudaFuncSetAttribute(k_edge2, cudaFuncAttributeMaxDynamicSharedMemorySize, SM_E2);

    k_zero_deg<<<(NNODE+255)/256, 256>>>();
    k_deg<<<(EDGES+255)/256, 256>>>(eidx);
    k_zh<<<NBATCH, 128>>>(z, lw, lb);
    k_hinit<<<NNODE, 128>>>(at, aw, ab);
    k_posinit<<<(NNODE*3+255)/256, 256>>>(ic);

    for (int l = 0; l < 2; l++){
        k_papb<<<NNODE/128, 256, SM_PAPB>>>(ew1, l);
        k_reld2<<<(EDGES+255)/256, 256>>>(eidx);
        k_zero_layer<<<(NNODE*HIDN+255)/256, 256>>>();
        k_edge1<<<(EDGES*HIDN)/256, 256>>>(ew1, eb1, eidx, l);
        k_edge2<<<EDGES/128, 256, SM_E2>>>(ew2, eb2, cw1, cb1, cw2, eidx, l);
        k_node<<<NNODE/128, 256, SM_NODE>>>(nw1, nb1, nw2, nb2, lg, lbn, l);
        k_posupd<<<(NNODE*3+255)/256, 256>>>();
    }
    k_head<<<NNODE/8, 64>>>(hw1, hb1, hw2, hb2, (float*)d_out);
}

// round 7
// speedup vs baseline: 1.1318x; 1.1318x over previous
#include <cuda_runtime.h>
#include <math.h>

#define HIDN 128
#define LATN 64
#define AFN 10
#define NBATCH 512
#define NATOMS 58
#define NNODE (NBATCH*NATOMS)     // 29696
#define EDGES (NNODE*16)          // 475136
#define AST 132                   // padded smem stride for transposed A tiles

// ---------------- scratch (device globals; no runtime allocation) ----------------
__device__ float g_h  [NNODE*HIDN];
__device__ float g_pa [NNODE*HIDN];
__device__ float g_pb [NNODE*HIDN];
__device__ float g_agg[NNODE*HIDN];
__device__ float g_zh [NBATCH*HIDN];
__device__ float g_rel[EDGES*3];
__device__ float g_d2 [EDGES];
__device__ float g_pos[NNODE*3];
__device__ float g_upd[NNODE*3];
__device__ float g_deg[NNODE];

__device__ __forceinline__ float siluf(float x){ return x / (1.0f + expf(-x)); }

// packed fp32x2 FMA: d = a*b + d (exact fp32 math, 2 lanes per instruction)
#define FMA2(d,a,b) asm("fma.rn.f32x2 %0, %1, %2, %0;" : "+l"(d) : "l"(a), "l"(b))

__device__ __forceinline__ void unpack8(const unsigned long long* a, float* o){
#pragma unroll
    for (int j = 0; j < 4; j++){
        unsigned int lo, hi;
        asm("mov.b64 {%0, %1}, %2;" : "=r"(lo), "=r"(hi) : "l"(a[j]));
        o[2*j]   = __uint_as_float(lo);
        o[2*j+1] = __uint_as_float(hi);
    }
}

// ---------------- tile helpers: 256 threads, block tile 128x128, thread tile 8x8 ----
// As is stored transposed: As[k*AST + r]  (k = reduction idx, r = row in tile)
__device__ __forceinline__ void stageA(const float* __restrict__ g, float* As, int tid){
#pragma unroll
    for (int i = 0; i < 16; i++){
        int idx4 = tid + i*256;          // 0..4095 float4s
        int r  = idx4 >> 5;              // row
        int kq = idx4 & 31;              // float4 index along K
        float4 v = ((const float4*)g)[r*32 + kq];
        int k0 = kq*4;
        As[(k0+0)*AST + r] = v.x;
        As[(k0+1)*AST + r] = v.y;
        As[(k0+2)*AST + r] = v.z;
        As[(k0+3)*AST + r] = v.w;
    }
}

__device__ __forceinline__ void stageB(const float* __restrict__ g, float* Bs, int tid){
#pragma unroll
    for (int i = 0; i < 16; i++){
        int f4 = tid + i*256;
        ((float4*)Bs)[f4] = ((const float4*)g)[f4];
    }
}

// 128-K GEMM on the 128x128 tile, 8x8 thread tile held as 8x4 packed f32x2 pairs
__device__ __forceinline__ void gemm128x2(const float* As, const float* Bs,
                                          int r0, int c0, unsigned long long acc[8][4]){
#pragma unroll 4
    for (int k = 0; k < 128; k++){
        float4 a0 = *(const float4*)(As + k*AST + r0);
        float4 a1 = *(const float4*)(As + k*AST + r0 + 4);
        ulonglong2 bA = *(const ulonglong2*)(Bs + k*HIDN + c0);
        ulonglong2 bB = *(const ulonglong2*)(Bs + k*HIDN + c0 + 4);
        float a[8] = {a0.x,a0.y,a0.z,a0.w,a1.x,a1.y,a1.z,a1.w};
#pragma unroll
        for (int i = 0; i < 8; i++){
            unsigned long long av;
            unsigned int ab = __float_as_uint(a[i]);
            asm("mov.b64 %0, {%1, %1};" : "=l"(av) : "r"(ab));
            FMA2(acc[i][0], av, bA.x);
            FMA2(acc[i][1], av, bA.y);
            FMA2(acc[i][2], av, bB.x);
            FMA2(acc[i][3], av, bB.y);
        }
    }
}

__device__ __forceinline__ void writeTile2(float* __restrict__ g, int r0, int c0,
                                           unsigned long long acc[8][4]){
#pragma unroll
    for (int i = 0; i < 8; i++){
        float o[8]; unpack8(acc[i], o);
        *(float4*)(g + (size_t)(r0+i)*HIDN + c0)     = make_float4(o[0],o[1],o[2],o[3]);
        *(float4*)(g + (size_t)(r0+i)*HIDN + c0 + 4) = make_float4(o[4],o[5],o[6],o[7]);
    }
}

// ---------------- init kernels ----------------
__global__ void k_zero_deg(){
    int i = blockIdx.x*blockDim.x + threadIdx.x;
    if (i < NNODE) g_deg[i] = 0.0f;
}
__global__ void k_deg(const int* __restrict__ eidx){
    int e = blockIdx.x*blockDim.x + threadIdx.x;
    if (e < EDGES) atomicAdd(&g_deg[eidx[e]], 1.0f);
}
__global__ void k_zh(const float* __restrict__ z, const float* __restrict__ lw,
                     const float* __restrict__ lb){
    int b = blockIdx.x, c = threadIdx.x;
    float acc = lb[c];
#pragma unroll 8
    for (int k = 0; k < LATN; k++) acc += z[b*LATN + k] * lw[k*HIDN + c];
    g_zh[b*HIDN + c] = acc;
}
__global__ void k_hinit(const float* __restrict__ at, const float* __restrict__ aw,
                        const float* __restrict__ ab){
    int n = blockIdx.x, c = threadIdx.x;
    float acc = g_zh[(n / NATOMS)*HIDN + c] + ab[c];
#pragma unroll
    for (int j = 0; j < AFN; j++) acc += at[n*AFN + j] * aw[j*HIDN + c];
    g_h[(size_t)n*HIDN + c] = acc;
}
__global__ void k_posinit(const float* __restrict__ ic){
    int i = blockIdx.x*blockDim.x + threadIdx.x;
    if (i < NNODE*3){
        int n = i / 3, j = i - n*3;
        g_pos[i] = ic[(n % NATOMS)*3 + j];
    }
}
__global__ void k_zero_layer(){
    int i = blockIdx.x*blockDim.x + threadIdx.x;
    if (i < NNODE*HIDN) g_agg[i] = 0.0f;
    if (i < NNODE*3)    g_upd[i] = 0.0f;
}

// ---------------- per-layer kernels ----------------
// pa = h @ W1a, pb = h @ W1b   (W1a = ew1 rows 0..127, W1b = rows 128..255)
__global__ void __launch_bounds__(256) k_papb(const float* __restrict__ ew1, int layer){
    extern __shared__ float sm[];
    float* As = sm;
    float* Bs = sm + 128*AST;
    int tid = threadIdx.x;
    int n0 = blockIdx.x*128;
    int r0 = (tid >> 4)*8, c0 = (tid & 15)*8;
    const float* W = ew1 + (size_t)layer*257*HIDN;

    stageA(g_h + (size_t)n0*HIDN, As, tid);
    stageB(W, Bs, tid);
    __syncthreads();
    unsigned long long acc[8][4] = {};
    gemm128x2(As, Bs, r0, c0, acc);
    writeTile2(g_pa + (size_t)n0*HIDN, r0, c0, acc);
    __syncthreads();
    stageB(W + 128*HIDN, Bs, tid);
    __syncthreads();
    unsigned long long acc2[8][4] = {};
    gemm128x2(As, Bs, r0, c0, acc2);
    writeTile2(g_pb + (size_t)n0*HIDN, r0, c0, acc2);
}

__global__ void k_reld2(const int* __restrict__ eidx){
    int e = blockIdx.x*blockDim.x + threadIdx.x;
    if (e >= EDGES) return;
    int r = eidx[e], c = eidx[EDGES + e];
    float rx = g_pos[r*3+0] - g_pos[c*3+0];
    float ry = g_pos[r*3+1] - g_pos[c*3+1];
    float rz = g_pos[r*3+2] - g_pos[c*3+2];
    float d2 = rx*rx + ry*ry + rz*rz;
    d2 = fminf(fmaxf(d2, 1e-6f), 1e6f);
    g_rel[e*3+0] = rx; g_rel[e*3+1] = ry; g_rel[e*3+2] = rz;
    g_d2[e] = d2;
}

// Fused edge pipeline per 128-edge tile:
//   h1 = silu(pa[row] + pb[col] + d2*w1c + eb1)         (gather, staged to SMEM)
//   m  = silu(h1 @ ew2 + eb2)
//   cw = clip(silu(m @ cw1 + cb1) @ cw2, -1, 1)
//   agg[row] += m ; upd[row] += cw * rel
__global__ void __launch_bounds__(256) k_edge2(const float* __restrict__ ew1,
        const float* __restrict__ eb1,  const float* __restrict__ ew2,
        const float* __restrict__ eb2,  const float* __restrict__ cw1,
        const float* __restrict__ cb1,  const float* __restrict__ cw2,
        const int* __restrict__ eidx, int layer){
    extern __shared__ float sm[];
    float* As    = sm;                    // 128*132
    float* Bs    = As + 128*AST;          // ew2
    float* Bs2   = Bs + 128*128;          // cw1
    float* red2  = Bs2 + 128*128;         // 128*17
    float* d2_s  = red2 + 128*17;         // 128
    float* w1c_s = d2_s + 128;            // 128
    float* eb1_s = w1c_s + 128;           // 128
    int*  rows_s = (int*)(eb1_s + 128);   // 128
    int*  cols_s = rows_s + 128;          // 128
    int tid = threadIdx.x;
    int e0 = blockIdx.x*128;
    int r0 = (tid >> 4)*8, c0 = (tid & 15)*8;

    stageB(ew2 + (size_t)layer*HIDN*HIDN, Bs, tid);
    stageB(cw1 + (size_t)layer*HIDN*HIDN, Bs2, tid);
    if (tid < 128){
        rows_s[tid] = eidx[e0 + tid];
        cols_s[tid] = eidx[EDGES + e0 + tid];
        d2_s[tid]   = g_d2[e0 + tid];
    } else {
        int c = tid - 128;
        w1c_s[c] = ew1[(size_t)layer*257*HIDN + 256*HIDN + c];
        eb1_s[c] = eb1[layer*HIDN + c];
    }
    __syncthreads();

    // fused edge-MLP-1: gather + silu, store transposed into As
    {
        int e  = tid >> 1;
        int ch = (tid & 1) * 64;
        int rw = rows_s[e], cl = cols_s[e];
        float d2 = d2_s[e];
        const float4* par = (const float4*)(g_pa + (size_t)rw*HIDN + ch);
        const float4* pbr = (const float4*)(g_pb + (size_t)cl*HIDN + ch);
#pragma unroll
        for (int q = 0; q < 16; q++){
            float4 va = par[q], vb = pbr[q];
            int c = ch + q*4;
            As[(c+0)*AST+e] = siluf(va.x+vb.x + d2*w1c_s[c+0] + eb1_s[c+0]);
            As[(c+1)*AST+e] = siluf(va.y+vb.y + d2*w1c_s[c+1] + eb1_s[c+1]);
            As[(c+2)*AST+e] = siluf(va.z+vb.z + d2*w1c_s[c+2] + eb1_s[c+2]);
            As[(c+3)*AST+e] = siluf(va.w+vb.w + d2*w1c_s[c+3] + eb1_s[c+3]);
        }
    }
    __syncthreads();

    unsigned long long acc[8][4] = {};
    gemm128x2(As, Bs, r0, c0, acc);
    float bb[8];
#pragma unroll
    for (int j = 0; j < 8; j++) bb[j] = eb2[layer*HIDN + c0 + j];
    float m[8][8];
#pragma unroll
    for (int i = 0; i < 8; i++){
        float o[8]; unpack8(acc[i], o);
#pragma unroll
        for (int j = 0; j < 8; j++) m[i][j] = siluf(o[j] + bb[j]);
    }
    __syncthreads();                    // all reads of As done

    // stage m transposed back into As for GEMM2
#pragma unroll
    for (int j = 0; j < 8; j++)
#pragma unroll
        for (int i = 0; i < 8; i++)
            As[(c0+j)*AST + r0 + i] = m[i][j];
    __syncthreads();

    unsigned long long acc2[8][4] = {};
    gemm128x2(As, Bs2, r0, c0, acc2);
    float cb[8], c2v[8];
#pragma unroll
    for (int j = 0; j < 8; j++){
        cb[j]  = cb1[layer*HIDN + c0 + j];
        c2v[j] = cw2[layer*HIDN + c0 + j];
    }
#pragma unroll
    for (int i = 0; i < 8; i++){
        float o[8]; unpack8(acc2[i], o);
        float p = 0.0f;
#pragma unroll
        for (int j = 0; j < 8; j++){
            float c1 = siluf(o[j] + cb[j]);
            p += c1 * c2v[j];
        }
        red2[(r0+i)*17 + (tid & 15)] = p;
    }
    __syncthreads();

    if (tid < 128){
        float s = 0.0f;
#pragma unroll
        for (int t = 0; t < 16; t++) s += red2[tid*17 + t];
        float cwv = fminf(fmaxf(s, -1.0f), 1.0f);
        int e = e0 + tid;
        int rw = rows_s[tid];
        atomicAdd(&g_upd[rw*3+0], cwv * g_rel[e*3+0]);
        atomicAdd(&g_upd[rw*3+1], cwv * g_rel[e*3+1]);
        atomicAdd(&g_upd[rw*3+2], cwv * g_rel[e*3+2]);
    }

    // agg[row] += m : coalesced (warp = one edge row, consecutive columns)
#pragma unroll 4
    for (int i = 0; i < 64; i++){
        int flat = tid + i*256;
        int e = flat >> 7, c = flat & 127;
        atomicAdd(&g_agg[(size_t)rows_s[e]*HIDN + c], As[c*AST + e]);
    }
}

// hn = LN( silu([h,agg]@nw1 + nb1) @ nw2 + nb2 )  -> written back into g_h
__global__ void __launch_bounds__(256) k_node(const float* __restrict__ nw1,
        const float* __restrict__ nb1, const float* __restrict__ nw2,
        const float* __restrict__ nb2, const float* __restrict__ lg,
        const float* __restrict__ lb, int layer){
    extern __shared__ float sm[];
    float* As   = sm;             // 128*132 (also reused as Hs)
    float* Bs   = As + 128*AST;   // 128*128
    float* mu_s = Bs + 128*128;   // 128
    float* rs_s = mu_s + 128;     // 128
    int tid = threadIdx.x;
    int n0 = blockIdx.x*128;
    int r0 = (tid >> 4)*8, c0 = (tid & 15)*8;
    const float* W1 = nw1 + (size_t)layer*256*HIDN;

    unsigned long long acc[8][4] = {};
    stageA(g_h + (size_t)n0*HIDN, As, tid);
    stageB(W1, Bs, tid);
    __syncthreads();
    gemm128x2(As, Bs, r0, c0, acc);
    __syncthreads();
    stageA(g_agg + (size_t)n0*HIDN, As, tid);
    stageB(W1 + 128*HIDN, Bs, tid);
    __syncthreads();
    gemm128x2(As, Bs, r0, c0, acc);
    __syncthreads();

    // t = silu(acc + nb1), staged transposed into As; Bs <- nw2
#pragma unroll
    for (int i = 0; i < 8; i++){
        float o[8]; unpack8(acc[i], o);
#pragma unroll
        for (int j = 0; j < 8; j++)
            As[(c0+j)*AST + r0 + i] = siluf(o[j] + nb1[layer*HIDN + c0 + j]);
    }
    stageB(nw2 + (size_t)layer*HIDN*HIDN, Bs, tid);
    __syncthreads();

    unsigned long long acc2[8][4] = {};
    gemm128x2(As, Bs, r0, c0, acc2);
    __syncthreads();                 // As reads done; reuse as Hs (row-major, stride AST)
#pragma unroll
    for (int i = 0; i < 8; i++){
        float o[8]; unpack8(acc2[i], o);
#pragma unroll
        for (int j = 0; j < 8; j++)
            As[(r0+i)*AST + c0 + j] = o[j] + nb2[layer*HIDN + c0 + j];
    }
    __syncthreads();

    if (tid < 128){
        float s = 0.0f, s2 = 0.0f;
        const float* row = As + tid*AST;
#pragma unroll 8
        for (int k = 0; k < 128; k++){ float v = row[k]; s += v; s2 += v*v; }
        float mu = s * (1.0f/128.0f);
        float var = s2 * (1.0f/128.0f) - mu*mu;
        mu_s[tid] = mu;
        rs_s[tid] = rsqrtf(var + 1e-5f);
    }
    __syncthreads();

#pragma unroll
    for (int i = 0; i < 16; i++){
        int f4 = tid + i*256;
        int r = f4 >> 5, cq = f4 & 31, c = cq*4;
        float4 v = *(float4*)(As + r*AST + c);
        float mu = mu_s[r], rs = rs_s[r];
        v.x = (v.x - mu)*rs*lg[layer*HIDN + c+0] + lb[layer*HIDN + c+0];
        v.y = (v.y - mu)*rs*lg[layer*HIDN + c+1] + lb[layer*HIDN + c+1];
        v.z = (v.z - mu)*rs*lg[layer*HIDN + c+2] + lb[layer*HIDN + c+2];
        v.w = (v.w - mu)*rs*lg[layer*HIDN + c+3] + lb[layer*HIDN + c+3];
        *(float4*)(g_h + (size_t)(n0+r)*HIDN + c) = v;
    }
}

__global__ void k_posupd(){
    int i = blockIdx.x*blockDim.x + threadIdx.x;
    if (i < NNODE*3){
        int n = i / 3;
        g_pos[i] += g_upd[i] / (g_deg[n] + 1e-6f);
    }
}

// out = pos + silu(h@hw1+hb1)@hw2 + hb2
__global__ void __launch_bounds__(64) k_head(const float* __restrict__ hw1,
        const float* __restrict__ hb1, const float* __restrict__ hw2,
        const float* __restrict__ hb2, float* __restrict__ out){
    __shared__ float t[64];
    int tid = threadIdx.x;
    for (int u = 0; u < 8; u++){
        int n = blockIdx.x*8 + u;
        float acc = hb1[tid];
        const float* hr = g_h + (size_t)n*HIDN;
#pragma unroll 8
        for (int k = 0; k < 128; k++) acc += hr[k] * hw1[k*64 + tid];
        t[tid] = siluf(acc);
        __syncthreads();
        if (tid < 3){
            float d = hb2[tid];
#pragma unroll 8
            for (int k = 0; k < 64; k++) d += t[k] * hw2[k*3 + tid];
            out[n*3 + tid] = g_pos[n*3 + tid] + d;
        }
        __syncthreads();
    }
}

// ---------------- host ----------------
extern "C" void kernel_launch(void* const* d_in, const int* in_sizes, int n_in,
                              void* d_out, int out_size){
    const float* z   = (const float*)d_in[0];
    const float* at  = (const float*)d_in[1];
    const int*   eidx = (const int*)d_in[2];
    const float* ic  = (const float*)d_in[3];
    const float* lw  = (const float*)d_in[4];
    const float* lb  = (const float*)d_in[5];
    const float* aw  = (const float*)d_in[6];
    const float* ab  = (const float*)d_in[7];
    const float* ew1 = (const float*)d_in[8];
    const float* eb1 = (const float*)d_in[9];
    const float* ew2 = (const float*)d_in[10];
    const float* eb2 = (const float*)d_in[11];
    const float* nw1 = (const float*)d_in[12];
    const float* nb1 = (const float*)d_in[13];
    const float* nw2 = (const float*)d_in[14];
    const float* nb2 = (const float*)d_in[15];
    const float* cw1 = (const float*)d_in[16];
    const float* cb1 = (const float*)d_in[17];
    const float* cw2 = (const float*)d_in[18];
    const float* lg  = (const float*)d_in[19];
    const float* lbn = (const float*)d_in[20];
    const float* hw1 = (const float*)d_in[21];
    const float* hb1 = (const float*)d_in[22];
    const float* hw2 = (const float*)d_in[23];
    const float* hb2 = (const float*)d_in[24];

    const int SM_PAPB = (128*AST + 128*128) * 4;                          // 133,120 B
    const int SM_NODE = (128*AST + 128*128 + 256) * 4;                    // 134,144 B
    const int SM_E2   = (128*AST + 2*128*128 + 128*17 + 3*128) * 4 + 256*4; // 209,920 B
    cudaFuncSetAttribute(k_papb,  cudaFuncAttributeMaxDynamicSharedMemorySize, SM_PAPB);
    cudaFuncSetAttribute(k_node,  cudaFuncAttributeMaxDynamicSharedMemorySize, SM_NODE);
    cudaFuncSetAttribute(k_edge2, cudaFuncAttributeMaxDynamicSharedMemorySize, SM_E2);

    k_zero_deg<<<(NNODE+255)/256, 256>>>();
    k_deg<<<(EDGES+255)/256, 256>>>(eidx);
    k_zh<<<NBATCH, 128>>>(z, lw, lb);
    k_hinit<<<NNODE, 128>>>(at, aw, ab);
    k_posinit<<<(NNODE*3+255)/256, 256>>>(ic);

    for (int l = 0; l < 2; l++){
        k_papb<<<NNODE/128, 256, SM_PAPB>>>(ew1, l);
        k_reld2<<<(EDGES+255)/256, 256>>>(eidx);
        k_zero_layer<<<(NNODE*HIDN+255)/256, 256>>>();
        k_edge2<<<EDGES/128, 256, SM_E2>>>(ew1, eb1, ew2, eb2, cw1, cb1, cw2, eidx, l);
        k_node<<<NNODE/128, 256, SM_NODE>>>(nw1, nb1, nw2, nb2, lg, lbn, l);
        k_posupd<<<(NNODE*3+255)/256, 256>>>();
    }
    k_head<<<NNODE/8, 64>>>(hw1, hb1, hw2, hb2, (float*)d_out);
}